// round 11
// baseline (speedup 1.0000x reference)
#include <cuda_runtime.h>
#include <stdint.h>

// HypervectorEngine: 512x8192 f32 -> 512x4096 f32 sparse sign output.
// seed = i ^ round(sig*1000) in [0,1024) -> 1024 distinct hypervectors.
// K1: bit-packed sign table; threefry IMAD adds + widemul rotations (R8, passing).
// K2: combine (R10 accumulate/merge, passing) + NEW plane-domain select:
//     binary-search threshold via 7-bit bitwise comparators + popc, zero atomics.
// RNG: JAX partitionable threefry, word_j = o0 ^ o1 of threefry(key,(0,j)). (verified R2)

#define NSAMP   100
#define QSAMP   25
#define DIMV    4096
#define KSEL    2048
#define LSIG    8192
#define NSEEDS  1024
#define WPR     (DIMV / 32)        // 128 packed words per hypervector
#define WP2     (WPR / 2)          // 64 word-pairs

__device__ uint32_t g_hv[NSEEDS * WPR];

__device__ __forceinline__ uint32_t addi(uint32_t a, uint32_t b, uint32_t one) {
    uint32_t d;
    asm("mad.lo.u32 %0, %1, %2, %3;" : "=r"(d) : "r"(a), "r"(one), "r"(b));
    return d;
}
__device__ __forceinline__ uint32_t xor3(uint32_t a, uint32_t b, uint32_t c) {
    return a ^ b ^ c;                       // 1 LOP3
}
__device__ __forceinline__ uint32_t maj3(uint32_t a, uint32_t b, uint32_t c) {
    return (a & b) | (c & (a | b));         // 1 LOP3
}
// rotl via widemul (fma pipe). pw = one<<r (opaque).
__device__ __forceinline__ uint32_t rotw(uint32_t x, uint32_t pw, uint32_t one) {
    uint64_t pr;
    asm("mul.wide.u32 %0, %1, %2;" : "=l"(pr) : "r"(x), "r"(pw));
    return addi((uint32_t)(pr >> 32), (uint32_t)pr, one);
}

// Bitwise 7-bit comparator: bit l set iff n_l >= C, n given as planes r[0..6].
// LSB-to-MSB recurrence: g' = maj3(r_k, g, splat(!c_k)).
__device__ __forceinline__ uint32_t geq_mask(const uint32_t* r, int C) {
    uint32_t g = 0xFFFFFFFFu;
#pragma unroll
    for (int k = 0; k < 7; k++) {
        uint32_t ck = ((C >> k) & 1) ? 0u : 0xFFFFFFFFu;
        g = maj3(r[k], g, ck);
    }
    return g;
}
// bit l set iff n_l == C
__device__ __forceinline__ uint32_t eqc_mask(const uint32_t* r, int C) {
    uint32_t e = 0xFFFFFFFFu;
#pragma unroll
    for (int k = 0; k < 7; k++) {
        uint32_t ck = ((C >> k) & 1) ? 0xFFFFFFFFu : 0u;
        e &= ~(r[k] ^ ck);
    }
    return e;
}

// JAX threefry2x32, key (0,42), counter (0,c1) -> derived key (fold_in). Cold path.
__device__ __forceinline__ void threefry_key(uint32_t c1, uint32_t& o0, uint32_t& o1)
{
    const uint32_t k0 = 0u, k1 = 42u, k2 = 0u ^ 42u ^ 0x1BD11BDAu;
    uint32_t x0 = k0, x1 = c1 + k1;
    #define R(r) { x0 += x1; x1 = __funnelshift_l(x1, x1, r); x1 ^= x0; }
    R(13) R(15) R(26) R(6)  x0 += k1; x1 += k2 + 1u;
    R(17) R(29) R(16) R(24) x0 += k2; x1 += k0 + 2u;
    R(13) R(15) R(26) R(6)  x0 += k0; x1 += k1 + 3u;
    R(17) R(29) R(16) R(24) x0 += k1; x1 += k2 + 4u;
    R(13) R(15) R(26) R(6)
    o0 = x0 + k2; o1 = x1 + k0 + 5u;
    #undef R
}

// ---------------- Kernel 1: build hypervector sign table (R8, passing) ----------------
__global__ void __launch_bounds__(256)
hv_table_kernel(uint32_t one)
{
    const int seed = blockIdx.x;
    const int t    = threadIdx.x;
    const int lane = t & 31;
    const int wrp  = t >> 5;

    __shared__ uint32_t sk0, sk1;
    if (t == 0) {
        uint32_t o0, o1;
        threefry_key((uint32_t)seed, o0, o1);
        sk0 = o0; sk1 = o1;
    }
    __syncthreads();
    const uint32_t k0 = sk0, k1 = sk1, k2 = k0 ^ k1 ^ 0x1BD11BDAu;
    const uint32_t k2p1 = k2 + 1u, k0p2 = k0 + 2u, k1p3 = k1 + 3u;
    const uint32_t k2p4 = k2 + 4u, k0p5 = k0 + 5u;
    const uint32_t k1t  = k1 + (uint32_t)t;
    const uint32_t pw29 = one << 29, pw24 = one << 24;

    uint32_t* dst = g_hv + (size_t)seed * WPR;
#pragma unroll
    for (int p = 0; p < DIMV / 256; p++) {
        uint32_t x0 = k0;
        uint32_t x1 = addi(k1t, (uint32_t)(p * 256), one);
        #define RB(r)  { x0 = addi(x0, x1, one); x1 = __funnelshift_l(x1, x1, r); x1 ^= x0; }
        #define RBW(pw){ x0 = addi(x0, x1, one); x1 = rotw(x1, pw, one); x1 ^= x0; }
        RB(13) RB(15) RB(26) RB(6)
        x0 = addi(x0, k1, one); x1 = addi(x1, k2p1, one);
        RB(17) RBW(pw29) RB(16) RBW(pw24)
        x0 = addi(x0, k2, one); x1 = addi(x1, k0p2, one);
        RB(13) RB(15) RB(26) RB(6)
        x0 = addi(x0, k0, one); x1 = addi(x1, k1p3, one);
        RB(17) RBW(pw29) RB(16) RBW(pw24)
        x0 = addi(x0, k1, one); x1 = addi(x1, k2p4, one);
        RB(13) RB(15) RB(26) RB(6)
        #undef RB
        #undef RBW
        const uint32_t o0 = addi(x0, k2, one);
        const uint32_t o1 = addi(x1, k0p5, one);
        const uint32_t word = __ballot_sync(0xFFFFFFFFu, (int)((o0 ^ o1) >> 31));
        if (lane == 0) dst[p * 8 + wrp] = word;
    }
}

// ---------------- Kernel 2: combine + plane-domain top-k select ----------------
#define C_THREADS 256

__global__ void __launch_bounds__(C_THREADS)
hv_combine_kernel(const float* __restrict__ sig, float* __restrict__ out)
{
    const int b = blockIdx.x;
    const int t = threadIdx.x;
    const int lane = t & 31;
    const int wid  = t >> 5;

    __shared__ int      sseed[NSAMP];
    __shared__ uint32_t spl[4][5][WPR];     // [quarter][plane][word], 10 KB
    __shared__ int      sred[2][8];         // double-buffered block-count
    __shared__ int      swsum[4];
    __shared__ uint32_t s_eq[WPR], s_gt[WPR], s_pos[WPR], s_neg[WPR];
    __shared__ int      s_base[WPR];

    if (t < NSAMP) {
        const int i   = t;
        const int idx = (i * (LSIG - 1)) / (NSAMP - 1);   // trunc of f32 linspace
        const float s = sig[(size_t)b * LSIG + idx];
        const int val = __float2int_rn(s * 1000.0f);      // jnp.round RNE
        sseed[i] = i ^ val;                                // in [0,1024)
    }
    __syncthreads();

    // ---- accumulate (R10, passing): thread -> word-pair wp, quarter qt ----
    {
        const int wp = t & (WP2 - 1);
        const int qt = t >> 6;                 // 0..3
        const int ibase = qt * QSAMP;
        const uint2* tbl2 = reinterpret_cast<const uint2*>(g_hv);

        uint32_t pa0=0,pa1=0,pa2=0,pa3=0,pa4=0;
        uint32_t pb0=0,pb1=0,pb2=0,pb3=0,pb4=0;
#pragma unroll
        for (int g = 0; g < QSAMP / 5; g++) {
            const int i0 = ibase + g * 5;
            uint2 v0 = tbl2[(size_t)sseed[i0    ] * WP2 + wp];
            uint2 v1 = tbl2[(size_t)sseed[i0 + 1] * WP2 + wp];
            uint2 v2 = tbl2[(size_t)sseed[i0 + 2] * WP2 + wp];
            uint2 v3 = tbl2[(size_t)sseed[i0 + 3] * WP2 + wp];
            uint2 v4 = tbl2[(size_t)sseed[i0 + 4] * WP2 + wp];
            {
                uint32_t s1 = xor3(v0.x, v1.x, v2.x);
                uint32_t c1 = maj3(v0.x, v1.x, v2.x);
                uint32_t g1 = xor3(s1, v3.x, v4.x);
                uint32_t c2 = maj3(s1, v3.x, v4.x);
                uint32_t g2 = c1 ^ c2;
                uint32_t g4 = c1 & c2;
                uint32_t cy = pa0 & g1;  pa0 ^= g1;
                uint32_t n1 = xor3(pa1, g2, cy); cy = maj3(pa1, g2, cy); pa1 = n1;
                uint32_t n2 = xor3(pa2, g4, cy); cy = maj3(pa2, g4, cy); pa2 = n2;
                uint32_t n3 = pa3 ^ cy;  cy &= pa3;  pa3 = n3;
                pa4 ^= cy;
            }
            {
                uint32_t s1 = xor3(v0.y, v1.y, v2.y);
                uint32_t c1 = maj3(v0.y, v1.y, v2.y);
                uint32_t g1 = xor3(s1, v3.y, v4.y);
                uint32_t c2 = maj3(s1, v3.y, v4.y);
                uint32_t g2 = c1 ^ c2;
                uint32_t g4 = c1 & c2;
                uint32_t cy = pb0 & g1;  pb0 ^= g1;
                uint32_t n1 = xor3(pb1, g2, cy); cy = maj3(pb1, g2, cy); pb1 = n1;
                uint32_t n2 = xor3(pb2, g4, cy); cy = maj3(pb2, g4, cy); pb2 = n2;
                uint32_t n3 = pb3 ^ cy;  cy &= pb3;  pb3 = n3;
                pb4 ^= cy;
            }
        }
        uint2* s2;
        s2 = reinterpret_cast<uint2*>(spl[qt][0]); s2[wp] = make_uint2(pa0, pb0);
        s2 = reinterpret_cast<uint2*>(spl[qt][1]); s2[wp] = make_uint2(pa1, pb1);
        s2 = reinterpret_cast<uint2*>(spl[qt][2]); s2[wp] = make_uint2(pa2, pb2);
        s2 = reinterpret_cast<uint2*>(spl[qt][3]); s2[wp] = make_uint2(pa3, pb3);
        s2 = reinterpret_cast<uint2*>(spl[qt][4]); s2[wp] = make_uint2(pa4, pb4);
    }
    __syncthreads();

    // ---- 4-way merge: t<128 owns word w=t, planes rp[0..6] (n = count of -1 bits) ----
    uint32_t rp[7];
    if (t < WPR) {
        const int w = t;
        uint32_t a0 = spl[0][0][w], a1 = spl[0][1][w], a2 = spl[0][2][w],
                 a3 = spl[0][3][w], a4 = spl[0][4][w];
        uint32_t b0 = spl[1][0][w], b1 = spl[1][1][w], b2 = spl[1][2][w],
                 b3 = spl[1][3][w], b4 = spl[1][4][w];
        uint32_t c0 = spl[2][0][w], c1 = spl[2][1][w], c2 = spl[2][2][w],
                 c3 = spl[2][3][w], c4 = spl[2][4][w];
        uint32_t d0 = spl[3][0][w], d1 = spl[3][1][w], d2 = spl[3][2][w],
                 d3 = spl[3][3][w], d4 = spl[3][4][w];

        uint32_t m0,m1,m2,m3,m4,m5, n0,n1,n2,n3,n4,n5, cy;
        m0 = a0 ^ b0;        cy = a0 & b0;
        m1 = xor3(a1,b1,cy); cy = maj3(a1,b1,cy);
        m2 = xor3(a2,b2,cy); cy = maj3(a2,b2,cy);
        m3 = xor3(a3,b3,cy); cy = maj3(a3,b3,cy);
        m4 = xor3(a4,b4,cy); cy = maj3(a4,b4,cy);
        m5 = cy;
        n0 = c0 ^ d0;        cy = c0 & d0;
        n1 = xor3(c1,d1,cy); cy = maj3(c1,d1,cy);
        n2 = xor3(c2,d2,cy); cy = maj3(c2,d2,cy);
        n3 = xor3(c3,d3,cy); cy = maj3(c3,d3,cy);
        n4 = xor3(c4,d4,cy); cy = maj3(c4,d4,cy);
        n5 = cy;

        rp[0] = m0 ^ n0;          cy = m0 & n0;
        rp[1] = xor3(m1,n1,cy);   cy = maj3(m1,n1,cy);
        rp[2] = xor3(m2,n2,cy);   cy = maj3(m2,n2,cy);
        rp[3] = xor3(m3,n3,cy);   cy = maj3(m3,n3,cy);
        rp[4] = xor3(m4,n4,cy);   cy = maj3(m4,n4,cy);
        rp[5] = xor3(m5,n5,cy);   cy = maj3(m5,n5,cy);
        rp[6] = cy;
    }

    // ---- binary search T = max v in [0,50] with count(|n-50| >= v) >= KSEL ----
    // cval = 100-2n, bin = |50-n|. f(0)=4096 >= KSEL always.
    int lo = 0, hi = 50;
    int buf = 0;
#pragma unroll
    for (int it = 0; it < 6; it++) {
        const int mid = (lo + hi + 1) >> 1;
        int my = 0;
        if (t < WPR)
            my = __popc(geq_mask(rp, 50 + mid)) + __popc(~geq_mask(rp, 51 - mid));
#pragma unroll
        for (int off = 16; off > 0; off >>= 1)
            my += __shfl_xor_sync(0xFFFFFFFFu, my, off);
        if (lane == 0) sred[buf][wid] = my;
        __syncthreads();
        int f = sred[buf][0] + sred[buf][1] + sred[buf][2] + sred[buf][3]
              + sred[buf][4] + sred[buf][5] + sred[buf][6] + sred[buf][7];
        if (f >= KSEL) lo = mid; else hi = mid - 1;
        buf ^= 1;
    }
    const int T = lo;

    // ---- quota = KSEL - count(|d| > T) = KSEL - f(T+1) ----
    {
        int my = 0;
        if (t < WPR)
            my = __popc(geq_mask(rp, 50 + T + 1)) + __popc(~geq_mask(rp, 50 - T));
#pragma unroll
        for (int off = 16; off > 0; off >>= 1)
            my += __shfl_xor_sync(0xFFFFFFFFu, my, off);
        if (lane == 0) sred[buf][wid] = my;
        __syncthreads();
    }
    const int fgt = sred[buf][0] + sred[buf][1] + sred[buf][2] + sred[buf][3]
                  + sred[buf][4] + sred[buf][5] + sred[buf][6] + sred[buf][7];
    const int quota = KSEL - fgt;

    // ---- masks + tie-rank scan over words (index order) ----
    if (t < WPR) {
        const uint32_t gt  = geq_mask(rp, 51 + T) | ~geq_mask(rp, 50 - T);
        const uint32_t eqh = eqc_mask(rp, 50 + T);
        const uint32_t eql = eqc_mask(rp, 50 - T);
        const uint32_t eq  = eqh | eql;            // T==0: eqh==eql, no double count
        const uint32_t pos = ~geq_mask(rp, 50);    // n < 50  -> +1
        const uint32_t neg = geq_mask(rp, 51);     // n > 50  -> -1

        const int wcnt = __popc(eq);
        int inc = wcnt;
#pragma unroll
        for (int off = 1; off < 32; off <<= 1) {
            int y = __shfl_up_sync(0xFFFFFFFFu, inc, off);
            if (lane >= off) inc += y;
        }
        if (lane == 31) swsum[wid] = inc;          // wid 0..3
        s_eq[t] = eq; s_gt[t] = gt; s_pos[t] = pos; s_neg[t] = neg;
        s_base[t] = inc - wcnt;                    // intra-warp exclusive
    }
    __syncthreads();

    // ---- write: thread t owns elements j = (t>>1)*32 + (t&1)*16 .. +15 ----
    const int w2 = t >> 1;
    const int hb = t & 1;
    const uint32_t eq = s_eq[w2], gt = s_gt[w2], pos = s_pos[w2], neg = s_neg[w2];

    int base = s_base[w2];
    {   // add warp-offset of word-warp (w2>>5) : sum of swsum below it
        const int ww = w2 >> 5;
        if (ww > 0) base += swsum[0];
        if (ww > 1) base += swsum[1];
        if (ww > 2) base += swsum[2];
    }
    int rank = base + (hb ? __popc(eq & 0xFFFFu) : 0);

    float4* orow = reinterpret_cast<float4*>(out + (size_t)b * DIMV + t * 16);
#pragma unroll
    for (int v4 = 0; v4 < 4; v4++) {
        float vv[4];
#pragma unroll
        for (int e = 0; e < 4; e++) {
            const int l = hb * 16 + v4 * 4 + e;
            const uint32_t bl = 1u << l;
            float v = 0.0f;
            if (gt & bl) {
                v = (pos & bl) ? 1.0f : -1.0f;
            } else if (eq & bl) {
                if (rank < quota)
                    v = (pos & bl) ? 1.0f : ((neg & bl) ? -1.0f : 0.0f);
                rank++;
            }
            vv[e] = v;
        }
        orow[v4] = make_float4(vv[0], vv[1], vv[2], vv[3]);
    }
}

extern "C" void kernel_launch(void* const* d_in, const int* in_sizes, int n_in,
                              void* d_out, int out_size)
{
    const float* sig = (const float*)d_in[0];
    float* out = (float*)d_out;
    const int B = in_sizes[0] / LSIG;   // 512
    hv_table_kernel<<<NSEEDS, 256>>>(1u);
    hv_combine_kernel<<<B, C_THREADS>>>(sig, out);
}